// round 5
// baseline (speedup 1.0000x reference)
#include <cuda_runtime.h>
#include <cstdint>

#define D        128
#define CD       3
#define NLAYERS  3
#define MAXN     65536
#define MAXE     1048576

#define SOSTRIDE 132   // padded row stride for the 128x128 smem tile

// ---------------- scratch (ping-pong node-feature buffers) ----------------
__device__ float g_x0  [(size_t)MAXN * D];
__device__ float g_x1  [(size_t)MAXN * D];
__device__ int   g_cnt [MAXN];
__device__ int   g_off [MAXN + 1];
__device__ int   g_srcs[MAXE];

// ---------------- CSR build ----------------
__global__ void hist_kernel(const int* __restrict__ dst, int* __restrict__ cnt, int E) {
    int i = blockIdx.x * blockDim.x + threadIdx.x;
    if (i < E) atomicAdd(&cnt[dst[i]], 1);
}

__global__ __launch_bounds__(1024) void scan_kernel(int* __restrict__ cnt, int* __restrict__ off,
                                                    int n, int E) {
    __shared__ int ssum[1024];
    int t = threadIdx.x;
    int C = (n + 1023) / 1024;
    int lo = t * C, hi = min(lo + C, n);
    int s = 0;
    for (int i = lo; i < hi; i++) s += cnt[i];
    ssum[t] = s;
    __syncthreads();
    for (int d = 1; d < 1024; d <<= 1) {
        int v = (t >= d) ? ssum[t - d] : 0;
        __syncthreads();
        ssum[t] += v;
        __syncthreads();
    }
    int base = ssum[t] - s;
    for (int i = lo; i < hi; i++) {
        int c = cnt[i];
        off[i] = base;
        cnt[i] = 0;          // reset -> cursor for fill
        base += c;
    }
    if (t == 1023) off[n] = E;
}

__global__ void fill_kernel(const int* __restrict__ src, const int* __restrict__ dst,
                            const int* __restrict__ off, int* __restrict__ cur,
                            int* __restrict__ srcs, int E) {
    int e = blockIdx.x * blockDim.x + threadIdx.x;
    if (e >= E) return;
    int d = dst[e];
    int p = atomicAdd(&cur[d], 1);
    srcs[off[d] + p] = src[e];
}

// ---------------- 3x3 Householder QR (LAPACK dlarfg convention) ----------------
__device__ __forceinline__ void qr3(const float A0[9], float Q[9]) {
    float a[9];
#pragma unroll
    for (int i = 0; i < 9; i++) a[i] = A0[i];

    float tau1 = 0.f, v1 = 0.f, v2 = 0.f;
    {
        float c0 = a[0], c1 = a[3], c2 = a[6];
        float xn2 = c1 * c1 + c2 * c2;
        if (xn2 > 0.f) {
            float nrm  = sqrtf(c0 * c0 + xn2);
            float beta = -copysignf(nrm, c0);
            tau1 = (beta - c0) / beta;
            float inv = 1.f / (c0 - beta);
            v1 = c1 * inv;
            v2 = c2 * inv;
#pragma unroll
            for (int c = 1; c < 3; c++) {
                float w = a[c] + v1 * a[3 + c] + v2 * a[6 + c];
                w *= tau1;
                a[c]     -= w;
                a[3 + c] -= w * v1;
                a[6 + c] -= w * v2;
            }
        }
    }
    float tau2 = 0.f, u2 = 0.f;
    {
        float alpha = a[4], x2 = a[7];
        if (x2 != 0.f) {
            float nrm  = sqrtf(alpha * alpha + x2 * x2);
            float beta = -copysignf(nrm, alpha);
            tau2 = (beta - alpha) / beta;
            u2   = x2 / (alpha - beta);
        }
    }
    float h11 = 1.f - tau2;
    float h12 = -tau2 * u2;
    float h22 = 1.f - tau2 * u2 * u2;
#pragma unroll
    for (int j = 0; j < 3; j++) {
        float h0 = (j == 0) ? 1.f : 0.f;
        float h1 = (j == 0) ? 0.f : ((j == 1) ? h11 : h12);
        float h2 = (j == 0) ? 0.f : ((j == 1) ? h12 : h22);
        float w  = tau1 * (h0 + v1 * h1 + v2 * h2);
        Q[0 * 3 + j] = h0 - w;
        Q[1 * 3 + j] = h1 - v1 * w;
        Q[2 * 3 + j] = h2 - v2 * w;
    }
}

// =======================================================================
// Fused layer kernel: gather-aggregate -> GEMM -> projections/QR updates
// NOTE: x (read) and out (write) MUST be distinct buffers (ping-pong).
// =======================================================================
__global__ __launch_bounds__(256, 2) void layer_kernel(
        const float4* __restrict__ x, const int* __restrict__ off,
        const int* __restrict__ srcs,
        const float* __restrict__ W,  const float* __restrict__ bl,
        const float* __restrict__ Wc, const float* __restrict__ bc,
        const float* __restrict__ WR, const float* __restrict__ bR,
        const float* __restrict__ Wt, const float* __restrict__ bt,
        float* __restrict__ out, const float* __restrict__ pos_in,
        float* __restrict__ pos, float* __restrict__ R, float* __restrict__ tv,
        int n, int first) {
    extern __shared__ float sm[];
    float* sO   = sm;                        // 128 * SOSTRIDE
    float* sW   = sO + 128 * SOSTRIDE;       // 32 * 128
    float* sWp  = sW + 32 * 128;             // 13 * 128
    float* sDeg = sWp + 13 * 128;            // 128

    int t    = threadIdx.x;
    int w    = t >> 5;
    int lane = t & 31;
    int row0 = blockIdx.x * 128;

    // phase 0: projection weights -> smem
    for (int i = t; i < 13 * D; i += 256) {
        int j = i >> 7, k = i & 127;
        float v;
        if (j == 0)      v = Wc[k];
        else if (j < 10) v = WR[k * 9 + (j - 1)];
        else             v = Wt[k * 3 + (j - 10)];
        sWp[j * D + k] = v;
    }

    // phase 1: gather-aggregate 16 nodes per warp into sO (row-major)
#pragma unroll 1
    for (int i = 0; i < 16; i++) {
        int local = w * 16 + i;
        int node  = row0 + local;
        if (node >= n) break;
        int j0 = __ldg(&off[node]);
        int j1 = __ldg(&off[node + 1]);
        float4 acc = make_float4(0.f, 0.f, 0.f, 0.f);
        int j = j0;
        for (; j + 4 <= j1; j += 4) {
            int s0 = __ldg(&srcs[j + 0]);
            int s1 = __ldg(&srcs[j + 1]);
            int s2 = __ldg(&srcs[j + 2]);
            int s3 = __ldg(&srcs[j + 3]);
            float4 v0 = __ldg(&x[(size_t)s0 * 32 + lane]);
            float4 v1 = __ldg(&x[(size_t)s1 * 32 + lane]);
            float4 v2 = __ldg(&x[(size_t)s2 * 32 + lane]);
            float4 v3 = __ldg(&x[(size_t)s3 * 32 + lane]);
            acc.x += v0.x + v1.x + v2.x + v3.x;
            acc.y += v0.y + v1.y + v2.y + v3.y;
            acc.z += v0.z + v1.z + v2.z + v3.z;
            acc.w += v0.w + v1.w + v2.w + v3.w;
        }
        for (; j < j1; j++) {
            int s = __ldg(&srcs[j]);
            float4 v = __ldg(&x[(size_t)s * 32 + lane]);
            acc.x += v.x; acc.y += v.y; acc.z += v.z; acc.w += v.w;
        }
        *(float4*)&sO[local * SOSTRIDE + lane * 4] = acc;
        if (lane == 0) sDeg[local] = (float)(j1 - j0);
    }

    // phase 2: GEMM  out_tile = sO(128x128) @ W(128x128)
    int tx = t & 15;
    int ty = t >> 4;
    int rb = ty * 8;
    int cb = tx * 8;

    float acc[8][8];
#pragma unroll
    for (int i = 0; i < 8; i++)
#pragma unroll
        for (int j = 0; j < 8; j++) acc[i][j] = 0.f;

    int lw_k = t >> 3;
    int lw_c = (t & 7) * 4;

#pragma unroll 1
    for (int k0 = 0; k0 < D; k0 += 32) {
#pragma unroll
        for (int q = 0; q < 4; q++) {
            int c = lw_c + q * 32;
            *(float4*)&sW[lw_k * D + c] = *(const float4*)&W[(size_t)(k0 + lw_k) * D + c];
        }
        __syncthreads();
#pragma unroll
        for (int kk = 0; kk < 32; kk++) {
            int k = k0 + kk;
            float a[8], b[8];
#pragma unroll
            for (int i = 0; i < 8; i++) a[i] = sO[(rb + i) * SOSTRIDE + k];
            *(float4*)&b[0] = *(const float4*)&sW[kk * D + cb];
            *(float4*)&b[4] = *(const float4*)&sW[kk * D + cb + 4];
#pragma unroll
            for (int i = 0; i < 8; i++)
#pragma unroll
                for (int j = 0; j < 8; j++) acc[i][j] += a[i] * b[j];
        }
        __syncthreads();
    }

    // epilogue: add deg*bias, write to gmem and back into sO
    float bfrag[8];
#pragma unroll
    for (int j = 0; j < 8; j++) bfrag[j] = bl[cb + j];

#pragma unroll
    for (int i = 0; i < 8; i++) {
        int r = row0 + rb + i;
        if (r < n) {
            float f = sDeg[rb + i];
            float4 o0, o1;
            o0.x = acc[i][0] + f * bfrag[0];
            o0.y = acc[i][1] + f * bfrag[1];
            o0.z = acc[i][2] + f * bfrag[2];
            o0.w = acc[i][3] + f * bfrag[3];
            o1.x = acc[i][4] + f * bfrag[4];
            o1.y = acc[i][5] + f * bfrag[5];
            o1.z = acc[i][6] + f * bfrag[6];
            o1.w = acc[i][7] + f * bfrag[7];
            *(float4*)&out[(size_t)r * D + cb]     = o0;
            *(float4*)&out[(size_t)r * D + cb + 4] = o1;
            *(float4*)&sO[(rb + i) * SOSTRIDE + cb]     = o0;
            *(float4*)&sO[(rb + i) * SOSTRIDE + cb + 4] = o1;
        }
    }
    __syncthreads();

    // phase 3: projections + pos/R/t updates (from smem out tile)
    float bc0 = bc[0];
    float bt0 = bt[0], bt1 = bt[1], bt2 = bt[2];

#pragma unroll 1
    for (int i = 0; i < 16; i++) {
        int local = w * 16 + i;
        int node  = row0 + local;
        if (node >= n) break;

        float4 xv = *(const float4*)&sO[local * SOSTRIDE + lane * 4];
        float p[13];
#pragma unroll
        for (int j = 0; j < 13; j++) {
            float4 wv = ((const float4*)&sWp[j * D])[lane];
            float s = xv.x * wv.x + xv.y * wv.y + xv.z * wv.z + xv.w * wv.w;
            s += __shfl_xor_sync(0xFFFFFFFF, s, 16);
            s += __shfl_xor_sync(0xFFFFFFFF, s, 8);
            s += __shfl_xor_sync(0xFFFFFFFF, s, 4);
            s += __shfl_xor_sync(0xFFFFFFFF, s, 2);
            s += __shfl_xor_sync(0xFFFFFFFF, s, 1);
            p[j] = s;
        }

        if (lane == 0) {
            float c = p[0] + bc0;
            if (first) {
                pos[node * 3 + 0] = pos_in[node * 3 + 0] + c;
                pos[node * 3 + 1] = pos_in[node * 3 + 1] + c;
                pos[node * 3 + 2] = pos_in[node * 3 + 2] + c;
                tv[node * 3 + 0] = p[10] + bt0;
                tv[node * 3 + 1] = p[11] + bt1;
                tv[node * 3 + 2] = p[12] + bt2;
            } else {
                pos[node * 3 + 0] += c;
                pos[node * 3 + 1] += c;
                pos[node * 3 + 2] += c;
                tv[node * 3 + 0] += p[10] + bt0;
                tv[node * 3 + 1] += p[11] + bt1;
                tv[node * 3 + 2] += p[12] + bt2;
            }

            float Aq[9], Q[9];
#pragma unroll
            for (int k = 0; k < 9; k++) Aq[k] = p[1 + k] + bR[k];
            qr3(Aq, Q);
            if (first) {
#pragma unroll
                for (int k = 0; k < 9; k++) R[(size_t)node * 9 + k] = Q[k];
            } else {
                float Ro[9];
#pragma unroll
                for (int k = 0; k < 9; k++) Ro[k] = R[(size_t)node * 9 + k];
                float Rn[9];
#pragma unroll
                for (int a2 = 0; a2 < 3; a2++)
#pragma unroll
                    for (int b2 = 0; b2 < 3; b2++)
                        Rn[a2 * 3 + b2] = Q[a2 * 3 + 0] * Ro[0 * 3 + b2]
                                        + Q[a2 * 3 + 1] * Ro[1 * 3 + b2]
                                        + Q[a2 * 3 + 2] * Ro[2 * 3 + b2];
#pragma unroll
                for (int k = 0; k < 9; k++) R[(size_t)node * 9 + k] = Rn[k];
            }
        }
    }
}

// ---------------- plain GEMM for final fc: out = A @ W + bias ----------------
#define BK 32
__global__ __launch_bounds__(256) void gemm_kernel(
        const float* __restrict__ A, const float* __restrict__ W,
        const float* __restrict__ bias, float* __restrict__ out, int n) {
    __shared__ float sA[BK][D + 4];
    __shared__ float sW[BK][D];

    int t    = threadIdx.x;
    int row0 = blockIdx.x * 128;
    int tx   = t & 15;
    int ty   = t >> 4;
    int rb   = ty * 8;
    int cb   = tx * 8;

    float acc[8][8];
#pragma unroll
    for (int i = 0; i < 8; i++)
#pragma unroll
        for (int j = 0; j < 8; j++) acc[i][j] = 0.f;

    int la_k = (t & 7) * 4;
    int la_r = t >> 3;
    int lw_k = t >> 3;
    int lw_c = (t & 7) * 4;

#pragma unroll 1
    for (int k0 = 0; k0 < D; k0 += BK) {
#pragma unroll
        for (int rr = 0; rr < 128; rr += 32) {
            int rloc = la_r + rr;
            int rg   = row0 + rloc;
            float4 v = make_float4(0.f, 0.f, 0.f, 0.f);
            if (rg < n) v = *(const float4*)&A[(size_t)rg * D + k0 + la_k];
            sA[la_k + 0][rloc] = v.x;
            sA[la_k + 1][rloc] = v.y;
            sA[la_k + 2][rloc] = v.z;
            sA[la_k + 3][rloc] = v.w;
        }
#pragma unroll
        for (int q = 0; q < 4; q++) {
            int c = lw_c + q * 32;
            *(float4*)&sW[lw_k][c] = *(const float4*)&W[(size_t)(k0 + lw_k) * D + c];
        }
        __syncthreads();

#pragma unroll
        for (int kk = 0; kk < BK; kk++) {
            float a[8], b[8];
            *(float4*)&a[0] = *(const float4*)&sA[kk][rb];
            *(float4*)&a[4] = *(const float4*)&sA[kk][rb + 4];
            *(float4*)&b[0] = *(const float4*)&sW[kk][cb];
            *(float4*)&b[4] = *(const float4*)&sW[kk][cb + 4];
#pragma unroll
            for (int i = 0; i < 8; i++)
#pragma unroll
                for (int j = 0; j < 8; j++) acc[i][j] += a[i] * b[j];
        }
        __syncthreads();
    }

    float bfrag[8];
#pragma unroll
    for (int j = 0; j < 8; j++) bfrag[j] = bias[cb + j];

#pragma unroll
    for (int i = 0; i < 8; i++) {
        int r = row0 + rb + i;
        if (r < n) {
            float4 o0, o1;
            o0.x = acc[i][0] + bfrag[0];
            o0.y = acc[i][1] + bfrag[1];
            o0.z = acc[i][2] + bfrag[2];
            o0.w = acc[i][3] + bfrag[3];
            o1.x = acc[i][4] + bfrag[4];
            o1.y = acc[i][5] + bfrag[5];
            o1.z = acc[i][6] + bfrag[6];
            o1.w = acc[i][7] + bfrag[7];
            *(float4*)&out[(size_t)r * D + cb]     = o0;
            *(float4*)&out[(size_t)r * D + cb + 4] = o1;
        }
    }
}

// ---------------- launch ----------------
extern "C" void kernel_launch(void* const* d_in, const int* in_sizes, int n_in,
                              void* d_out, int out_size) {
    const float* x   = (const float*)d_in[0];
    const float* pos = (const float*)d_in[1];
    const int*   ei  = (const int*)d_in[2];
    const float* Wl  = (const float*)d_in[3];
    const float* bl  = (const float*)d_in[4];
    const float* Wc  = (const float*)d_in[5];
    const float* bc  = (const float*)d_in[6];
    const float* WR  = (const float*)d_in[7];
    const float* bR  = (const float*)d_in[8];
    const float* Wt  = (const float*)d_in[9];
    const float* bt  = (const float*)d_in[10];
    const float* Wf  = (const float*)d_in[11];
    const float* bf  = (const float*)d_in[12];

    int n = in_sizes[0] / D;
    int E = in_sizes[2] / 2;
    const int* src = ei;
    const int* dst = ei + E;

    float* zout = (float*)d_out;
    float* pout = zout + (size_t)n * D;
    float* Rout = pout + (size_t)n * 3;
    float* tout = Rout + (size_t)n * 9;

    float *x0, *x1;
    int *cnt, *off, *srcs;
    cudaGetSymbolAddress((void**)&x0,   g_x0);
    cudaGetSymbolAddress((void**)&x1,   g_x1);
    cudaGetSymbolAddress((void**)&cnt,  g_cnt);
    cudaGetSymbolAddress((void**)&off,  g_off);
    cudaGetSymbolAddress((void**)&srcs, g_srcs);

    int smem_bytes = (128 * SOSTRIDE + 32 * 128 + 13 * 128 + 128) * 4;
    cudaFuncSetAttribute(layer_kernel, cudaFuncAttributeMaxDynamicSharedMemorySize,
                         smem_bytes);

    // ---- CSR build ----
    cudaMemsetAsync(cnt, 0, (size_t)n * sizeof(int), 0);
    hist_kernel<<<(E + 255) / 256, 256>>>(dst, cnt, E);
    scan_kernel<<<1, 1024>>>(cnt, off, n, E);
    fill_kernel<<<(E + 255) / 256, 256>>>(src, dst, off, cnt, srcs, E);

    // ---- fused layers (ping-pong buffers to avoid RAW race) ----
    int blocks = (n + 127) / 128;
    const float* xcur = x;
    float* bufs[2] = { x0, x1 };
    float* xb = nullptr;
    for (int l = 0; l < NLAYERS; l++) {
        xb = bufs[l & 1];
        layer_kernel<<<blocks, 256, smem_bytes>>>(
            (const float4*)xcur, off, srcs,
            Wl + (size_t)l * D * D, bl + (size_t)l * D,
            Wc + (size_t)l * D,     bc + l,
            WR + (size_t)l * D * 9, bR + (size_t)l * 9,
            Wt + (size_t)l * D * 3, bt + (size_t)l * 3,
            xb, pos, pout, Rout, tout, n, l == 0 ? 1 : 0);
        xcur = xb;
    }

    // ---- final fc ----
    gemm_kernel<<<blocks, 256>>>(xb, Wf, bf, zout, n);
}

// round 7
// speedup vs baseline: 1.7065x; 1.7065x over previous
#include <cuda_runtime.h>
#include <cstdint>

#define D        128
#define CD       3
#define NLAYERS  3
#define MAXN     65536
#define MAXE     1048576

#define SOS 132                    // padded row stride for smem out tile
#define SMEM_FLOATS (128 * SOS + 13 * 128)   // sO + sWp

// ---------------- scratch ----------------
__device__ float g_agg [(size_t)MAXN * D];
__device__ float g_xb  [(size_t)MAXN * D];
__device__ int   g_cnt [MAXN];
__device__ int   g_off [MAXN + 1];
__device__ int   g_srcs[MAXE];

// ---------------- CSR build ----------------
__global__ void hist_kernel(const int* __restrict__ dst, int* __restrict__ cnt, int E) {
    int i = blockIdx.x * blockDim.x + threadIdx.x;
    if (i < E) atomicAdd(&cnt[dst[i]], 1);
}

__global__ __launch_bounds__(1024) void scan_kernel(int* __restrict__ cnt, int* __restrict__ off,
                                                    int n, int E) {
    __shared__ int ssum[1024];
    int t = threadIdx.x;
    int C = (n + 1023) / 1024;
    int lo = t * C, hi = min(lo + C, n);
    int s = 0;
    for (int i = lo; i < hi; i++) s += cnt[i];
    ssum[t] = s;
    __syncthreads();
    for (int d = 1; d < 1024; d <<= 1) {
        int v = (t >= d) ? ssum[t - d] : 0;
        __syncthreads();
        ssum[t] += v;
        __syncthreads();
    }
    int base = ssum[t] - s;
    for (int i = lo; i < hi; i++) {
        int c = cnt[i];
        off[i] = base;
        cnt[i] = 0;          // reset -> cursor for fill
        base += c;
    }
    if (t == 1023) off[n] = E;
}

__global__ void fill_kernel(const int* __restrict__ src, const int* __restrict__ dst,
                            const int* __restrict__ off, int* __restrict__ cur,
                            int* __restrict__ srcs, int E) {
    int e = blockIdx.x * blockDim.x + threadIdx.x;
    if (e >= E) return;
    int d = dst[e];
    int p = atomicAdd(&cur[d], 1);
    srcs[off[d] + p] = src[e];
}

// ---------------- gather aggregation: agg[i] = sum_{e: dst=i} x[src[e]] ----------------
__global__ __launch_bounds__(256) void aggregate_kernel(
        const float4* __restrict__ x, const int* __restrict__ off,
        const int* __restrict__ srcs, float4* __restrict__ agg, int n) {
    int node = blockIdx.x * 8 + (threadIdx.x >> 5);
    if (node >= n) return;
    int lane = threadIdx.x & 31;
    int j0 = __ldg(&off[node]);
    int j1 = __ldg(&off[node + 1]);

    float4 acc = make_float4(0.f, 0.f, 0.f, 0.f);
    int j = j0;
    for (; j + 4 <= j1; j += 4) {
        int s0 = __ldg(&srcs[j + 0]);
        int s1 = __ldg(&srcs[j + 1]);
        int s2 = __ldg(&srcs[j + 2]);
        int s3 = __ldg(&srcs[j + 3]);
        float4 v0 = __ldg(&x[(size_t)s0 * 32 + lane]);
        float4 v1 = __ldg(&x[(size_t)s1 * 32 + lane]);
        float4 v2 = __ldg(&x[(size_t)s2 * 32 + lane]);
        float4 v3 = __ldg(&x[(size_t)s3 * 32 + lane]);
        acc.x += v0.x + v1.x + v2.x + v3.x;
        acc.y += v0.y + v1.y + v2.y + v3.y;
        acc.z += v0.z + v1.z + v2.z + v3.z;
        acc.w += v0.w + v1.w + v2.w + v3.w;
    }
    for (; j < j1; j++) {
        int s = __ldg(&srcs[j]);
        float4 v = __ldg(&x[(size_t)s * 32 + lane]);
        acc.x += v.x; acc.y += v.y; acc.z += v.z; acc.w += v.w;
    }
    agg[(size_t)node * 32 + lane] = acc;
}

// ---------------- 3x3 Householder QR (LAPACK dlarfg convention) ----------------
__device__ __forceinline__ void qr3(const float A0[9], float Q[9]) {
    float a[9];
#pragma unroll
    for (int i = 0; i < 9; i++) a[i] = A0[i];

    float tau1 = 0.f, v1 = 0.f, v2 = 0.f;
    {
        float c0 = a[0], c1 = a[3], c2 = a[6];
        float xn2 = c1 * c1 + c2 * c2;
        if (xn2 > 0.f) {
            float nrm  = sqrtf(c0 * c0 + xn2);
            float beta = -copysignf(nrm, c0);
            tau1 = (beta - c0) / beta;
            float inv = 1.f / (c0 - beta);
            v1 = c1 * inv;
            v2 = c2 * inv;
#pragma unroll
            for (int c = 1; c < 3; c++) {
                float w = a[c] + v1 * a[3 + c] + v2 * a[6 + c];
                w *= tau1;
                a[c]     -= w;
                a[3 + c] -= w * v1;
                a[6 + c] -= w * v2;
            }
        }
    }
    float tau2 = 0.f, u2 = 0.f;
    {
        float alpha = a[4], x2 = a[7];
        if (x2 != 0.f) {
            float nrm  = sqrtf(alpha * alpha + x2 * x2);
            float beta = -copysignf(nrm, alpha);
            tau2 = (beta - alpha) / beta;
            u2   = x2 / (alpha - beta);
        }
    }
    float h11 = 1.f - tau2;
    float h12 = -tau2 * u2;
    float h22 = 1.f - tau2 * u2 * u2;
#pragma unroll
    for (int j = 0; j < 3; j++) {
        float h0 = (j == 0) ? 1.f : 0.f;
        float h1 = (j == 0) ? 0.f : ((j == 1) ? h11 : h12);
        float h2 = (j == 0) ? 0.f : ((j == 1) ? h12 : h22);
        float w  = tau1 * (h0 + v1 * h1 + v2 * h2);
        Q[0 * 3 + j] = h0 - w;
        Q[1 * 3 + j] = h1 - v1 * w;
        Q[2 * 3 + j] = h2 - v2 * w;
    }
}

// =======================================================================
// GEMM + fused per-node epilogue.
//   mode 0: out = A@W + bias              (final fc, no projections)
//   mode 1: out = A@W + deg*bias, then projections; first layer (init writes)
//   mode 2: same but accumulate pos/R/t
// Dynamic smem: sO[128*SOS] (overlaid with sA/sW in main loop), sWp[13*128]
// =======================================================================
__global__ __launch_bounds__(256) void gemm_fused(
        const float* __restrict__ A, const float* __restrict__ W,
        const float* __restrict__ bias, const int* __restrict__ off,
        float* __restrict__ out,
        const float* __restrict__ Wc, const float* __restrict__ bc,
        const float* __restrict__ WR, const float* __restrict__ bR,
        const float* __restrict__ Wt, const float* __restrict__ bt,
        const float* __restrict__ pos_in,
        float* __restrict__ pos, float* __restrict__ R, float* __restrict__ tv,
        int n, int mode) {
    extern __shared__ float sm[];
    float* sO  = sm;                 // 128*SOS floats (epilogue out tile)
    float* sA  = sm;                 // 32*132 overlaid
    float* sW  = sm + 32 * SOS;      // 32*128 overlaid
    float* sWp = sm + 128 * SOS;     // 13*128 projection weights

    int t    = threadIdx.x;
    int row0 = blockIdx.x * 128;
    int tx   = t & 15;
    int ty   = t >> 4;
    int rb   = ty * 8;
    int cb   = tx * 8;

    // load projection weights (above the sA/sW overlay, safe during main loop)
    if (mode != 0) {
        for (int i = t; i < 13 * D; i += 256) {
            int j = i >> 7, k = i & 127;
            float v;
            if (j == 0)      v = Wc[k];
            else if (j < 10) v = WR[k * 9 + (j - 1)];
            else             v = Wt[k * 3 + (j - 10)];
            sWp[j * D + k] = v;
        }
    }

    float acc[8][8];
#pragma unroll
    for (int i = 0; i < 8; i++)
#pragma unroll
        for (int j = 0; j < 8; j++) acc[i][j] = 0.f;

    int la_k = (t & 7) * 4;
    int la_r = t >> 3;
    int lw_k = t >> 3;
    int lw_c = (t & 7) * 4;

#pragma unroll 1
    for (int k0 = 0; k0 < D; k0 += 32) {
#pragma unroll
        for (int rr = 0; rr < 128; rr += 32) {
            int rloc = la_r + rr;
            int rg   = row0 + rloc;
            float4 v = make_float4(0.f, 0.f, 0.f, 0.f);
            if (rg < n) v = *(const float4*)&A[(size_t)rg * D + k0 + la_k];
            sA[(la_k + 0) * SOS + rloc] = v.x;
            sA[(la_k + 1) * SOS + rloc] = v.y;
            sA[(la_k + 2) * SOS + rloc] = v.z;
            sA[(la_k + 3) * SOS + rloc] = v.w;
        }
#pragma unroll
        for (int q = 0; q < 4; q++) {
            int c = lw_c + q * 32;
            *(float4*)&sW[lw_k * D + c] = *(const float4*)&W[(size_t)(k0 + lw_k) * D + c];
        }
        __syncthreads();

#pragma unroll
        for (int kk = 0; kk < 32; kk++) {
            float a[8], b[8];
            *(float4*)&a[0] = *(const float4*)&sA[kk * SOS + rb];
            *(float4*)&a[4] = *(const float4*)&sA[kk * SOS + rb + 4];
            *(float4*)&b[0] = *(const float4*)&sW[kk * D + cb];
            *(float4*)&b[4] = *(const float4*)&sW[kk * D + cb + 4];
#pragma unroll
            for (int i = 0; i < 8; i++)
#pragma unroll
                for (int j = 0; j < 8; j++) acc[i][j] += a[i] * b[j];
        }
        __syncthreads();
    }

    float bfrag[8];
#pragma unroll
    for (int j = 0; j < 8; j++) bfrag[j] = bias[cb + j];

#pragma unroll
    for (int i = 0; i < 8; i++) {
        int r = row0 + rb + i;
        if (r < n) {
            float f = 1.0f;
            if (mode != 0) f = (float)(__ldg(&off[r + 1]) - __ldg(&off[r]));
            float4 o0, o1;
            o0.x = acc[i][0] + f * bfrag[0];
            o0.y = acc[i][1] + f * bfrag[1];
            o0.z = acc[i][2] + f * bfrag[2];
            o0.w = acc[i][3] + f * bfrag[3];
            o1.x = acc[i][4] + f * bfrag[4];
            o1.y = acc[i][5] + f * bfrag[5];
            o1.z = acc[i][6] + f * bfrag[6];
            o1.w = acc[i][7] + f * bfrag[7];
            *(float4*)&out[(size_t)r * D + cb]     = o0;
            *(float4*)&out[(size_t)r * D + cb + 4] = o1;
            if (mode != 0) {
                *(float4*)&sO[(rb + i) * SOS + cb]     = o0;
                *(float4*)&sO[(rb + i) * SOS + cb + 4] = o1;
            }
        }
    }

    if (mode == 0) return;
    __syncthreads();

    // ---- fused projections + pos/R/t updates ----
    int w    = t >> 5;
    int lane = t & 31;
    int first = (mode == 1);
    float bc0 = bc[0];
    float bt0 = bt[0], bt1 = bt[1], bt2 = bt[2];

#pragma unroll 1
    for (int i = 0; i < 16; i++) {
        int local = w * 16 + i;
        int node  = row0 + local;
        if (node >= n) break;

        float4 xv = *(const float4*)&sO[local * SOS + lane * 4];
        float p[13];
#pragma unroll
        for (int j = 0; j < 13; j++) {
            float4 wv = ((const float4*)&sWp[j * D])[lane];
            float s = xv.x * wv.x + xv.y * wv.y + xv.z * wv.z + xv.w * wv.w;
            s += __shfl_xor_sync(0xFFFFFFFF, s, 16);
            s += __shfl_xor_sync(0xFFFFFFFF, s, 8);
            s += __shfl_xor_sync(0xFFFFFFFF, s, 4);
            s += __shfl_xor_sync(0xFFFFFFFF, s, 2);
            s += __shfl_xor_sync(0xFFFFFFFF, s, 1);
            p[j] = s;
        }

        if (lane == 0) {
            float c = p[0] + bc0;
            if (first) {
                pos[node * 3 + 0] = pos_in[node * 3 + 0] + c;
                pos[node * 3 + 1] = pos_in[node * 3 + 1] + c;
                pos[node * 3 + 2] = pos_in[node * 3 + 2] + c;
                tv[node * 3 + 0] = p[10] + bt0;
                tv[node * 3 + 1] = p[11] + bt1;
                tv[node * 3 + 2] = p[12] + bt2;
            } else {
                pos[node * 3 + 0] += c;
                pos[node * 3 + 1] += c;
                pos[node * 3 + 2] += c;
                tv[node * 3 + 0] += p[10] + bt0;
                tv[node * 3 + 1] += p[11] + bt1;
                tv[node * 3 + 2] += p[12] + bt2;
            }

            float Aq[9], Q[9];
#pragma unroll
            for (int k = 0; k < 9; k++) Aq[k] = p[1 + k] + bR[k];
            qr3(Aq, Q);
            if (first) {
#pragma unroll
                for (int k = 0; k < 9; k++) R[(size_t)node * 9 + k] = Q[k];
            } else {
                float Ro[9];
#pragma unroll
                for (int k = 0; k < 9; k++) Ro[k] = R[(size_t)node * 9 + k];
                float Rn[9];
#pragma unroll
                for (int a2 = 0; a2 < 3; a2++)
#pragma unroll
                    for (int b2 = 0; b2 < 3; b2++)
                        Rn[a2 * 3 + b2] = Q[a2 * 3 + 0] * Ro[0 * 3 + b2]
                                        + Q[a2 * 3 + 1] * Ro[1 * 3 + b2]
                                        + Q[a2 * 3 + 2] * Ro[2 * 3 + b2];
#pragma unroll
                for (int k = 0; k < 9; k++) R[(size_t)node * 9 + k] = Rn[k];
            }
        }
    }
}

// ---------------- launch ----------------
extern "C" void kernel_launch(void* const* d_in, const int* in_sizes, int n_in,
                              void* d_out, int out_size) {
    const float* x   = (const float*)d_in[0];
    const float* pos = (const float*)d_in[1];
    const int*   ei  = (const int*)d_in[2];
    const float* Wl  = (const float*)d_in[3];
    const float* bl  = (const float*)d_in[4];
    const float* Wc  = (const float*)d_in[5];
    const float* bc  = (const float*)d_in[6];
    const float* WR  = (const float*)d_in[7];
    const float* bR  = (const float*)d_in[8];
    const float* Wt  = (const float*)d_in[9];
    const float* bt  = (const float*)d_in[10];
    const float* Wf  = (const float*)d_in[11];
    const float* bf  = (const float*)d_in[12];

    int n = in_sizes[0] / D;
    int E = in_sizes[2] / 2;
    const int* src = ei;
    const int* dst = ei + E;

    float* zout = (float*)d_out;
    float* pout = zout + (size_t)n * D;
    float* Rout = pout + (size_t)n * 3;
    float* tout = Rout + (size_t)n * 9;

    float *agg, *xb;
    int *cnt, *off, *srcs;
    cudaGetSymbolAddress((void**)&agg,  g_agg);
    cudaGetSymbolAddress((void**)&xb,   g_xb);
    cudaGetSymbolAddress((void**)&cnt,  g_cnt);
    cudaGetSymbolAddress((void**)&off,  g_off);
    cudaGetSymbolAddress((void**)&srcs, g_srcs);

    int smem_bytes = SMEM_FLOATS * 4;
    cudaFuncSetAttribute(gemm_fused, cudaFuncAttributeMaxDynamicSharedMemorySize, smem_bytes);

    // ---- CSR build ----
    cudaMemsetAsync(cnt, 0, (size_t)n * sizeof(int), 0);
    hist_kernel<<<(E + 255) / 256, 256>>>(dst, cnt, E);
    scan_kernel<<<1, 1024>>>(cnt, off, n, E);
    fill_kernel<<<(E + 255) / 256, 256>>>(src, dst, off, cnt, srcs, E);

    // ---- layers ----
    int blocks = (n + 127) / 128;
    const float* xcur = x;
    for (int l = 0; l < NLAYERS; l++) {
        aggregate_kernel<<<(n + 7) / 8, 256>>>((const float4*)xcur, off, srcs, (float4*)agg, n);
        gemm_fused<<<blocks, 256, smem_bytes>>>(
            agg, Wl + (size_t)l * D * D, bl + (size_t)l * D, off, xb,
            Wc + (size_t)l * D,      bc + l,
            WR + (size_t)l * D * 9,  bR + (size_t)l * 9,
            Wt + (size_t)l * D * 3,  bt + (size_t)l * 3,
            pos, pout, Rout, tout, n, l == 0 ? 1 : 2);
        xcur = xb;
    }

    // ---- final fc ----
    gemm_fused<<<blocks, 256, smem_bytes>>>(
        xb, Wf, bf, nullptr, zout,
        nullptr, nullptr, nullptr, nullptr, nullptr, nullptr,
        nullptr, nullptr, nullptr, nullptr, n, 0);
}